// round 7
// baseline (speedup 1.0000x reference)
#include <cuda_runtime.h>
#include <cuda_fp16.h>
#include <cstdint>

#define DEV __device__ __forceinline__

// ============================ constants ============================
static constexpr int NTILES   = 2048;   // 262144 / 128
static constexpr int TILE_M   = 128;
static constexpr int NTHREADS = 256;    // 8 warps, each owns 16 rows
static constexpr int NCTAS    = 296;    // 2 per SM (148 SMs)

// SMEM layout in u32 units.
// Paired-B layout per layer (KF even): [n_group][k_pair][lane][4] u32
//   -> one LDS.128 per lane yields B fragments for k=2*k_pair and 2*k_pair+1.
// L5 (KF=1) keeps [lane][2].
static constexpr int SM_L1 = 0;                 // 16 n x 8 pairs x 128 u32 -> 16384
static constexpr int SM_L2 = 16384;             // 8 n x 4 pairs            -> 4096
static constexpr int SM_L3 = 20480;             // 4 n x 2 pairs            -> 1024
static constexpr int SM_L4 = 21504;             // 2 n x 1 pair             -> 256
static constexpr int SM_L5 = 21760;             // 1 frag [lane][2]         -> 64
static constexpr int SM_B1 = 21824;             // biases (f32)
static constexpr int SM_B2 = 21952;
static constexpr int SM_B3 = 22016;
static constexpr int SM_B4 = 22048;
static constexpr int SM_B5 = 22064;
static constexpr int SM_B6 = 22072;
static constexpr int SM_B7 = 22076;
static constexpr int SM_W6 = 22080;             // 32 f32 (8x4 row-major)
static constexpr int SM_W7 = 22112;             // 4 f32
static constexpr int SM_U32_TOTAL = 22128;
static constexpr int SMEM_BYTES = SM_U32_TOTAL * 4;   // 88512

// ============================ mma helper ============================
// m16n8k16 f16 x f16 -> f32.  Fragment layout (lane l, g=l>>2, t=l&3):
//   A: a0 = row g   k{2t,2t+1} | a1 = row g+8 k{2t,2t+1} | a2 = row g k{2t+8,2t+9} | a3 = row g+8 k{2t+8,2t+9}
//   B: b0 = k{2t,2t+1} col g   | b1 = k{2t+8,2t+9} col g
//   D: c0 = row g col 2t | c1 = row g col 2t+1 | c2 = row g+8 col 2t | c3 = row g+8 col 2t+1
// D layout == next layer's A layout, so activations stay in registers across layers.
DEV void mma16816(float d[4], const uint32_t a[4], uint32_t b0, uint32_t b1) {
    asm volatile(
        "mma.sync.aligned.m16n8k16.row.col.f32.f16.f16.f32 "
        "{%0,%1,%2,%3}, {%4,%5,%6,%7}, {%8,%9}, {%0,%1,%2,%3};\n"
        : "+f"(d[0]), "+f"(d[1]), "+f"(d[2]), "+f"(d[3])
        : "r"(a[0]), "r"(a[1]), "r"(a[2]), "r"(a[3]), "r"(b0), "r"(b1));
}

DEV uint32_t pack_h2(float a, float b) {
    __half2 h = __floats2half2_rn(a, b);
    return *reinterpret_cast<uint32_t*>(&h);
}

// ============================ weight prepack ============================
// W stored global as (K, N) row-major (n contiguous).
// Paired destination: block p = n*KF2 + k2 holds 128 u32: lane*4 + q, where
//   q in 0..3: k = 2*k2 + (q>>1), reg = q&1.
// PERM_K (layer 1 only): fragment k-col (2t + 8r + j) <-> global k-col (4t + 2r + j),
// making lane t's four elements one contiguous float4 in x.
template <int K, int N, bool PERM_K>
DEV void prepack_paired(uint32_t* __restrict__ dst, const float* __restrict__ W, int tid) {
    constexpr int KF = K / 16, NF = N / 8, KF2 = KF / 2;
    for (int i = tid; i < NF * KF2 * 128; i += NTHREADS) {
        int p = i >> 7, rem = i & 127, lane = rem >> 2, q = rem & 3;
        int n = p / KF2, k2 = p % KF2;
        int kk = 2 * k2 + (q >> 1), reg = q & 1;
        int g = lane >> 2, t = lane & 3;
        int krow = PERM_K ? (kk * 16 + 4 * t + 2 * reg)
                          : (kk * 16 + 2 * t + 8 * reg);
        int ncol = n * 8 + g;
        dst[p * 128 + lane * 4 + q] = pack_h2(W[krow * N + ncol], W[(krow + 1) * N + ncol]);
    }
}

// L5: single fragment, [lane][2]
DEV void prepack_single(uint32_t* __restrict__ dst, const float* __restrict__ W, int tid) {
    constexpr int N = 8;
    for (int i = tid; i < 64; i += NTHREADS) {
        int lane = i >> 1, reg = i & 1;
        int g = lane >> 2, t = lane & 3;
        int krow = 2 * t + 8 * reg;
        dst[lane * 2 + reg] = pack_h2(W[krow * N + g], W[(krow + 1) * N + g]);
    }
}

// ============================ generic middle layer ============================
// Ain: packed A fragments (KF k-steps); paired-B weights; bias+relu -> next A frags.
template <int KF, int NF>
DEV void layer_fwd(const uint32_t* __restrict__ bfrag, const float* __restrict__ bias,
                   const uint32_t* __restrict__ Ain, uint32_t* __restrict__ Aout, int lane) {
    constexpr int KF2 = KF / 2;
    const int t = lane & 3;
    float D[NF][4];
    #pragma unroll
    for (int n = 0; n < NF; ++n) { D[n][0] = D[n][1] = D[n][2] = D[n][3] = 0.f; }
    #pragma unroll
    for (int k2 = 0; k2 < KF2; ++k2) {
        #pragma unroll
        for (int n = 0; n < NF; ++n) {
            uint4 b = *reinterpret_cast<const uint4*>(bfrag + (n * KF2 + k2) * 128 + lane * 4);
            mma16816(D[n], Ain + 4 * (2 * k2),     b.x, b.y);
            mma16816(D[n], Ain + 4 * (2 * k2 + 1), b.z, b.w);
        }
    }
    #pragma unroll
    for (int n = 0; n < NF; ++n) {
        float bb0 = bias[8 * n + 2 * t], bb1 = bias[8 * n + 2 * t + 1];
        uint32_t lo = pack_h2(fmaxf(D[n][0] + bb0, 0.f), fmaxf(D[n][1] + bb1, 0.f));  // row g
        uint32_t hi = pack_h2(fmaxf(D[n][2] + bb0, 0.f), fmaxf(D[n][3] + bb1, 0.f));  // row g+8
        Aout[(n >> 1) * 4 + (n & 1) * 2 + 0] = lo;
        Aout[(n >> 1) * 4 + (n & 1) * 2 + 1] = hi;
    }
}

// ============================ kernel ============================
__global__ void __launch_bounds__(NTHREADS, 2)
fused_mlp_kernel(const float* __restrict__ x,
                 const float* __restrict__ W1g, const float* __restrict__ b1g,
                 const float* __restrict__ W2g, const float* __restrict__ b2g,
                 const float* __restrict__ W3g, const float* __restrict__ b3g,
                 const float* __restrict__ W4g, const float* __restrict__ b4g,
                 const float* __restrict__ W5g, const float* __restrict__ b5g,
                 const float* __restrict__ W6g, const float* __restrict__ b6g,
                 const float* __restrict__ W7g, const float* __restrict__ b7g,
                 float* __restrict__ out) {
    extern __shared__ uint32_t sm[];
    float* sf = reinterpret_cast<float*>(sm);

    const int tid  = threadIdx.x;
    const int wid  = tid >> 5;
    const int lane = tid & 31;
    const int g    = lane >> 2;
    const int t    = lane & 3;

    // -------- prepack weights into paired-fragment SMEM --------
    prepack_paired<256, 128, true >(sm + SM_L1, W1g, tid);   // K-permuted (matches LDG.128 x path)
    prepack_paired<128, 64,  false>(sm + SM_L2, W2g, tid);
    prepack_paired<64,  32,  false>(sm + SM_L3, W3g, tid);
    prepack_paired<32,  16,  false>(sm + SM_L4, W4g, tid);
    prepack_single(sm + SM_L5, W5g, tid);
    if (tid < 128) sf[SM_B1 + tid] = b1g[tid];
    if (tid < 64)  sf[SM_B2 + tid] = b2g[tid];
    if (tid < 32)  sf[SM_B3 + tid] = b3g[tid];
    if (tid < 16)  sf[SM_B4 + tid] = b4g[tid];
    if (tid < 8)   sf[SM_B5 + tid] = b5g[tid];
    if (tid < 4)   sf[SM_B6 + tid] = b6g[tid];
    if (tid < 1)   sf[SM_B7 + tid] = b7g[tid];
    if (tid < 32)  sf[SM_W6 + tid] = W6g[tid];   // (8,4) row-major
    if (tid < 4)   sf[SM_W7 + tid] = W7g[tid];   // (4,1)
    __syncthreads();

    const float* b1s = sf + SM_B1;
    const float* b2s = sf + SM_B2;
    const float* b3s = sf + SM_B3;
    const float* b4s = sf + SM_B4;
    const float* b5s = sf + SM_B5;
    const float* b6s = sf + SM_B6;
    const float  b7v = sf[SM_B7];
    const float* W6s = sf + SM_W6;
    const float* W7s = sf + SM_W7;

    // -------- main loop: each warp independently pushes its 16 rows through all layers --------
    for (int tile = blockIdx.x; tile < NTILES; tile += gridDim.x) {
        const int row0 = tile * TILE_M + wid * 16;

        // ---- L1: [16 x 256] @ W1 -> 16 x 128 ----
        float D[16][4];
        #pragma unroll
        for (int n = 0; n < 16; ++n) { D[n][0] = D[n][1] = D[n][2] = D[n][3] = 0.f; }

        // Lane reads float4 at (row g, global cols 16k+4t..4t+3) and (row g+8, same).
        // With the K-permutation this IS the A fragment: a0=(x,y), a2=(z,w), a1/a3 from row g+8.
        const float4* xr0 = reinterpret_cast<const float4*>(x + (size_t)(row0 + g) * 256) + t;
        const float4* xr1 = reinterpret_cast<const float4*>(x + (size_t)(row0 + g + 8) * 256) + t;
        #pragma unroll
        for (int k2 = 0; k2 < 8; ++k2) {
            float4 v0a = xr0[(2 * k2) * 4];
            float4 v1a = xr1[(2 * k2) * 4];
            float4 v0b = xr0[(2 * k2 + 1) * 4];
            float4 v1b = xr1[(2 * k2 + 1) * 4];
            uint32_t A0[4], A1[4];
            A0[0] = pack_h2(v0a.x, v0a.y);  A0[1] = pack_h2(v1a.x, v1a.y);
            A0[2] = pack_h2(v0a.z, v0a.w);  A0[3] = pack_h2(v1a.z, v1a.w);
            A1[0] = pack_h2(v0b.x, v0b.y);  A1[1] = pack_h2(v1b.x, v1b.y);
            A1[2] = pack_h2(v0b.z, v0b.w);  A1[3] = pack_h2(v1b.z, v1b.w);
            #pragma unroll
            for (int n = 0; n < 16; ++n) {
                uint4 b = *reinterpret_cast<const uint4*>(sm + SM_L1 + (n * 8 + k2) * 128 + lane * 4);
                mma16816(D[n], A0, b.x, b.y);
                mma16816(D[n], A1, b.z, b.w);
            }
        }
        uint32_t A2[32];
        #pragma unroll
        for (int n = 0; n < 16; ++n) {
            float bb0 = b1s[8 * n + 2 * t], bb1 = b1s[8 * n + 2 * t + 1];
            A2[(n >> 1) * 4 + (n & 1) * 2 + 0] = pack_h2(fmaxf(D[n][0] + bb0, 0.f), fmaxf(D[n][1] + bb1, 0.f));
            A2[(n >> 1) * 4 + (n & 1) * 2 + 1] = pack_h2(fmaxf(D[n][2] + bb0, 0.f), fmaxf(D[n][3] + bb1, 0.f));
        }

        // ---- L2..L4 ----
        uint32_t A3[16], A4[8], A5[4];
        layer_fwd<8, 8>(sm + SM_L2, b2s, A2, A3, lane);
        layer_fwd<4, 4>(sm + SM_L3, b3s, A3, A4, lane);
        layer_fwd<2, 2>(sm + SM_L4, b4s, A4, A5, lane);

        // ---- L5: [16 x 16] @ W5 -> 16 x 8 ----
        float d5[4] = {0.f, 0.f, 0.f, 0.f};
        {
            uint2 b = *reinterpret_cast<const uint2*>(sm + SM_L5 + lane * 2);
            mma16816(d5, A5, b.x, b.y);
        }

        // ---- L6 + L7 + sigmoid (scalar, 4-lane butterfly per row) ----
        float h0 = fmaxf(d5[0] + b5s[2 * t], 0.f);       // row g,   col 2t
        float h1 = fmaxf(d5[1] + b5s[2 * t + 1], 0.f);   // row g,   col 2t+1
        float h2 = fmaxf(d5[2] + b5s[2 * t], 0.f);       // row g+8, col 2t
        float h3 = fmaxf(d5[3] + b5s[2 * t + 1], 0.f);   // row g+8, col 2t+1

        float pa[4], pb[4];
        #pragma unroll
        for (int j = 0; j < 4; ++j) {
            pa[j] = h0 * W6s[(2 * t) * 4 + j] + h1 * W6s[(2 * t + 1) * 4 + j];
            pb[j] = h2 * W6s[(2 * t) * 4 + j] + h3 * W6s[(2 * t + 1) * 4 + j];
        }
        #pragma unroll
        for (int mask = 1; mask <= 2; mask <<= 1) {
            #pragma unroll
            for (int j = 0; j < 4; ++j) {
                pa[j] += __shfl_xor_sync(0xFFFFFFFFu, pa[j], mask);
                pb[j] += __shfl_xor_sync(0xFFFFFFFFu, pb[j], mask);
            }
        }
        float za = b7v, zb = b7v;
        #pragma unroll
        for (int j = 0; j < 4; ++j) {
            za += fmaxf(pa[j] + b6s[j], 0.f) * W7s[j];
            zb += fmaxf(pb[j] + b6s[j], 0.f) * W7s[j];
        }
        if (t == 0) {
            float* o = out + row0;
            o[g]     = 1.0f / (1.0f + __expf(-za));
            o[g + 8] = 1.0f / (1.0f + __expf(-zb));
        }
    }
}

// ============================ launch ============================
extern "C" void kernel_launch(void* const* d_in, const int* in_sizes, int n_in,
                              void* d_out, int out_size) {
    cudaFuncSetAttribute(fused_mlp_kernel,
                         cudaFuncAttributeMaxDynamicSharedMemorySize, SMEM_BYTES);
    fused_mlp_kernel<<<NCTAS, NTHREADS, SMEM_BYTES>>>(
        (const float*)d_in[0],
        (const float*)d_in[1],  (const float*)d_in[2],
        (const float*)d_in[3],  (const float*)d_in[4],
        (const float*)d_in[5],  (const float*)d_in[6],
        (const float*)d_in[7],  (const float*)d_in[8],
        (const float*)d_in[9],  (const float*)d_in[10],
        (const float*)d_in[11], (const float*)d_in[12],
        (const float*)d_in[13], (const float*)d_in[14],
        (float*)d_out);
}

// round 9
// speedup vs baseline: 1.4545x; 1.4545x over previous
#include <cuda_runtime.h>
#include <cuda_fp16.h>
#include <cstdint>

#define DEV __device__ __forceinline__

// ============================ constants ============================
static constexpr int TILE_M   = 256;    // per-CTA rows per iteration (8 warps x 32 rows)
static constexpr int NTILES   = 262144 / TILE_M;   // 1024
static constexpr int NTHREADS = 256;    // 8 warps, each owns 32 rows (two 16-row m-tiles)
static constexpr int NCTAS    = 148;    // 1 per SM -> 255 regs/thread available

// SMEM layout in u32 units.
// B fragments per layer: [n_group][k_step][lane][2] u32 (lane-contiguous -> LDS.64, conflict-free)
static constexpr int SM_L1 = 0;                 // 16 n x 16 k frags -> 16384 u32
static constexpr int SM_L2 = 16384;             // 8 x 8             -> 4096
static constexpr int SM_L3 = 20480;             // 4 x 4             -> 1024
static constexpr int SM_L4 = 21504;             // 2 x 2             -> 256
static constexpr int SM_L5 = 21760;             // 1 x 1             -> 64
static constexpr int SM_B1 = 21824;             // biases (f32)
static constexpr int SM_B2 = 21952;
static constexpr int SM_B3 = 22016;
static constexpr int SM_B4 = 22048;
static constexpr int SM_B5 = 22064;
static constexpr int SM_B6 = 22072;
static constexpr int SM_B7 = 22076;
static constexpr int SM_W6 = 22080;             // 32 f32 (8x4 row-major)
static constexpr int SM_W7 = 22112;             // 4 f32
static constexpr int SM_U32_TOTAL = 22128;
static constexpr int SMEM_BYTES = SM_U32_TOTAL * 4;   // 88512

// ============================ mma helper ============================
// m16n8k16 f16 x f16 -> f32.  Fragment layout (lane l, g=l>>2, t=l&3):
//   A: a0 = row g   k{2t,2t+1} | a1 = row g+8 k{2t,2t+1} | a2 = row g k{2t+8,2t+9} | a3 = row g+8 k{2t+8,2t+9}
//   B: b0 = k{2t,2t+1} col g   | b1 = k{2t+8,2t+9} col g
//   D: c0 = row g col 2t | c1 = row g col 2t+1 | c2 = row g+8 col 2t | c3 = row g+8 col 2t+1
// D layout == next layer's A layout, so activations stay in registers across layers.
// M=32 per warp: two independent 16-row m-tiles SHARE each B fragment load.
DEV void mma16816(float d[4], const uint32_t a[4], uint32_t b0, uint32_t b1) {
    asm volatile(
        "mma.sync.aligned.m16n8k16.row.col.f32.f16.f16.f32 "
        "{%0,%1,%2,%3}, {%4,%5,%6,%7}, {%8,%9}, {%0,%1,%2,%3};\n"
        : "+f"(d[0]), "+f"(d[1]), "+f"(d[2]), "+f"(d[3])
        : "r"(a[0]), "r"(a[1]), "r"(a[2]), "r"(a[3]), "r"(b0), "r"(b1));
}

DEV uint32_t pack_h2(float a, float b) {
    __half2 h = __floats2half2_rn(a, b);
    return *reinterpret_cast<uint32_t*>(&h);
}

// ============================ weight prepack ============================
// W stored global as (K, N) row-major (n contiguous).  Destination fragment f = n*KF + k.
// PERM_K (layer 1 only): fragment k-col (2t + 8r + j) <-> global k-col (4t + 2r + j),
// so lane t's four A elements are one contiguous float4 in x (LDG.128).
template <int K, int N, bool PERM_K>
DEV void prepack(uint32_t* __restrict__ dst, const float* __restrict__ W, int tid) {
    constexpr int KF = K / 16, NF = N / 8;
    for (int i = tid; i < KF * NF * 64; i += NTHREADS) {
        int f = i >> 6, rem = i & 63, lane = rem >> 1, reg = rem & 1;
        int n = f / KF, kk = f % KF;
        int g = lane >> 2, t = lane & 3;
        int krow = PERM_K ? (kk * 16 + 4 * t + 2 * reg)
                          : (kk * 16 + 2 * t + 8 * reg);
        int ncol = n * 8 + g;
        dst[f * 64 + lane * 2 + reg] = pack_h2(W[krow * N + ncol], W[(krow + 1) * N + ncol]);
    }
}

// ============================ generic middle layer (two m-tiles) ============================
// One B LDS.64 per (n,k) feeds BOTH m-tiles: B bytes halved per row vs M=16.
template <int KF, int NF>
DEV void layer_fwd2(const uint32_t* __restrict__ bfrag, const float* __restrict__ bias,
                    const uint32_t* __restrict__ Ain0, const uint32_t* __restrict__ Ain1,
                    uint32_t* __restrict__ Aout0, uint32_t* __restrict__ Aout1, int lane) {
    const int t = lane & 3;
    float D0[NF][4], D1[NF][4];
    #pragma unroll
    for (int n = 0; n < NF; ++n) {
        D0[n][0] = D0[n][1] = D0[n][2] = D0[n][3] = 0.f;
        D1[n][0] = D1[n][1] = D1[n][2] = D1[n][3] = 0.f;
    }
    #pragma unroll
    for (int k = 0; k < KF; ++k) {
        #pragma unroll
        for (int n = 0; n < NF; ++n) {
            uint2 b = *reinterpret_cast<const uint2*>(bfrag + ((n * KF + k) * 32 + lane) * 2);
            mma16816(D0[n], Ain0 + 4 * k, b.x, b.y);
            mma16816(D1[n], Ain1 + 4 * k, b.x, b.y);
        }
    }
    #pragma unroll
    for (int n = 0; n < NF; ++n) {
        float bb0 = bias[8 * n + 2 * t], bb1 = bias[8 * n + 2 * t + 1];
        int o = (n >> 1) * 4 + (n & 1) * 2;
        Aout0[o + 0] = pack_h2(fmaxf(D0[n][0] + bb0, 0.f), fmaxf(D0[n][1] + bb1, 0.f));
        Aout0[o + 1] = pack_h2(fmaxf(D0[n][2] + bb0, 0.f), fmaxf(D0[n][3] + bb1, 0.f));
        Aout1[o + 0] = pack_h2(fmaxf(D1[n][0] + bb0, 0.f), fmaxf(D1[n][1] + bb1, 0.f));
        Aout1[o + 1] = pack_h2(fmaxf(D1[n][2] + bb0, 0.f), fmaxf(D1[n][3] + bb1, 0.f));
    }
}

// ============================ kernel ============================
__global__ void __launch_bounds__(NTHREADS, 1)
fused_mlp_kernel(const float* __restrict__ x,
                 const float* __restrict__ W1g, const float* __restrict__ b1g,
                 const float* __restrict__ W2g, const float* __restrict__ b2g,
                 const float* __restrict__ W3g, const float* __restrict__ b3g,
                 const float* __restrict__ W4g, const float* __restrict__ b4g,
                 const float* __restrict__ W5g, const float* __restrict__ b5g,
                 const float* __restrict__ W6g, const float* __restrict__ b6g,
                 const float* __restrict__ W7g, const float* __restrict__ b7g,
                 float* __restrict__ out) {
    extern __shared__ uint32_t sm[];
    float* sf = reinterpret_cast<float*>(sm);

    const int tid  = threadIdx.x;
    const int wid  = tid >> 5;
    const int lane = tid & 31;
    const int g    = lane >> 2;
    const int t    = lane & 3;

    // -------- prepack weights into per-fragment SMEM --------
    prepack<256, 128, true >(sm + SM_L1, W1g, tid);   // K-permuted (matches LDG.128 x path)
    prepack<128, 64,  false>(sm + SM_L2, W2g, tid);
    prepack<64,  32,  false>(sm + SM_L3, W3g, tid);
    prepack<32,  16,  false>(sm + SM_L4, W4g, tid);
    prepack<16,  8,   false>(sm + SM_L5, W5g, tid);
    if (tid < 128) sf[SM_B1 + tid] = b1g[tid];
    if (tid < 64)  sf[SM_B2 + tid] = b2g[tid];
    if (tid < 32)  sf[SM_B3 + tid] = b3g[tid];
    if (tid < 16)  sf[SM_B4 + tid] = b4g[tid];
    if (tid < 8)   sf[SM_B5 + tid] = b5g[tid];
    if (tid < 4)   sf[SM_B6 + tid] = b6g[tid];
    if (tid < 1)   sf[SM_B7 + tid] = b7g[tid];
    if (tid < 32)  sf[SM_W6 + tid] = W6g[tid];   // (8,4) row-major
    if (tid < 4)   sf[SM_W7 + tid] = W7g[tid];   // (4,1)
    __syncthreads();

    const float* b1s = sf + SM_B1;
    const float* b2s = sf + SM_B2;
    const float* b3s = sf + SM_B3;
    const float* b4s = sf + SM_B4;
    const float* b5s = sf + SM_B5;
    const float* b6s = sf + SM_B6;
    const float  b7v = sf[SM_B7];
    const float* W6s = sf + SM_W6;
    const float* W7s = sf + SM_W7;

    // -------- main loop: each warp pushes its 32 rows (2 m-tiles) through all layers --------
    for (int tile = blockIdx.x; tile < NTILES; tile += gridDim.x) {
        const int row0 = tile * TILE_M + wid * 32;

        // ---- L1: [32 x 256] @ W1 -> 32 x 128 ----
        float D0[16][4], D1[16][4];
        #pragma unroll
        for (int n = 0; n < 16; ++n) {
            D0[n][0] = D0[n][1] = D0[n][2] = D0[n][3] = 0.f;
            D1[n][0] = D1[n][1] = D1[n][2] = D1[n][3] = 0.f;
        }

        // Lane reads float4 at (row, global cols 16k+4t..4t+3) for rows g, g+8, g+16, g+24.
        // With the K-permutation this IS the A fragment: a0=(x,y), a2=(z,w), a1/a3 from row+8.
        const float4* xr0 = reinterpret_cast<const float4*>(x + (size_t)(row0 + g)      * 256) + t;
        const float4* xr1 = reinterpret_cast<const float4*>(x + (size_t)(row0 + g + 8)  * 256) + t;
        const float4* xr2 = reinterpret_cast<const float4*>(x + (size_t)(row0 + g + 16) * 256) + t;
        const float4* xr3 = reinterpret_cast<const float4*>(x + (size_t)(row0 + g + 24) * 256) + t;
        #pragma unroll
        for (int k = 0; k < 16; ++k) {
            float4 v0 = xr0[k * 4];
            float4 v1 = xr1[k * 4];
            float4 v2 = xr2[k * 4];
            float4 v3 = xr3[k * 4];
            uint32_t A0[4], A1[4];
            A0[0] = pack_h2(v0.x, v0.y);  A0[1] = pack_h2(v1.x, v1.y);
            A0[2] = pack_h2(v0.z, v0.w);  A0[3] = pack_h2(v1.z, v1.w);
            A1[0] = pack_h2(v2.x, v2.y);  A1[1] = pack_h2(v3.x, v3.y);
            A1[2] = pack_h2(v2.z, v2.w);  A1[3] = pack_h2(v3.z, v3.w);
            #pragma unroll
            for (int n = 0; n < 16; ++n) {
                uint2 b = *reinterpret_cast<const uint2*>(sm + SM_L1 + ((n * 16 + k) * 32 + lane) * 2);
                mma16816(D0[n], A0, b.x, b.y);
                mma16816(D1[n], A1, b.x, b.y);
            }
        }
        uint32_t A2_0[32], A2_1[32];
        #pragma unroll
        for (int n = 0; n < 16; ++n) {
            float bb0 = b1s[8 * n + 2 * t], bb1 = b1s[8 * n + 2 * t + 1];
            int o = (n >> 1) * 4 + (n & 1) * 2;
            A2_0[o + 0] = pack_h2(fmaxf(D0[n][0] + bb0, 0.f), fmaxf(D0[n][1] + bb1, 0.f));
            A2_0[o + 1] = pack_h2(fmaxf(D0[n][2] + bb0, 0.f), fmaxf(D0[n][3] + bb1, 0.f));
            A2_1[o + 0] = pack_h2(fmaxf(D1[n][0] + bb0, 0.f), fmaxf(D1[n][1] + bb1, 0.f));
            A2_1[o + 1] = pack_h2(fmaxf(D1[n][2] + bb0, 0.f), fmaxf(D1[n][3] + bb1, 0.f));
        }

        // ---- L2..L4 ----
        uint32_t A3_0[16], A3_1[16], A4_0[8], A4_1[8], A5_0[4], A5_1[4];
        layer_fwd2<8, 8>(sm + SM_L2, b2s, A2_0, A2_1, A3_0, A3_1, lane);
        layer_fwd2<4, 4>(sm + SM_L3, b3s, A3_0, A3_1, A4_0, A4_1, lane);
        layer_fwd2<2, 2>(sm + SM_L4, b4s, A4_0, A4_1, A5_0, A5_1, lane);

        // ---- L5: [32 x 16] @ W5 -> 32 x 8 ----
        float d5a[4] = {0.f, 0.f, 0.f, 0.f};
        float d5b[4] = {0.f, 0.f, 0.f, 0.f};
        {
            uint2 b = *reinterpret_cast<const uint2*>(sm + SM_L5 + lane * 2);
            mma16816(d5a, A5_0, b.x, b.y);
            mma16816(d5b, A5_1, b.x, b.y);
        }

        // ---- L6 + L7 + sigmoid (scalar, 4-lane butterfly; 4 rows per lane group) ----
        float bb0 = b5s[2 * t], bb1 = b5s[2 * t + 1];
        float h[4][2];
        h[0][0] = fmaxf(d5a[0] + bb0, 0.f); h[0][1] = fmaxf(d5a[1] + bb1, 0.f);  // row g
        h[1][0] = fmaxf(d5a[2] + bb0, 0.f); h[1][1] = fmaxf(d5a[3] + bb1, 0.f);  // row g+8
        h[2][0] = fmaxf(d5b[0] + bb0, 0.f); h[2][1] = fmaxf(d5b[1] + bb1, 0.f);  // row g+16
        h[3][0] = fmaxf(d5b[2] + bb0, 0.f); h[3][1] = fmaxf(d5b[3] + bb1, 0.f);  // row g+24

        float p[4][4];
        #pragma unroll
        for (int r = 0; r < 4; ++r)
            #pragma unroll
            for (int j = 0; j < 4; ++j)
                p[r][j] = h[r][0] * W6s[(2 * t) * 4 + j] + h[r][1] * W6s[(2 * t + 1) * 4 + j];
        #pragma unroll
        for (int mask = 1; mask <= 2; mask <<= 1)
            #pragma unroll
            for (int r = 0; r < 4; ++r)
                #pragma unroll
                for (int j = 0; j < 4; ++j)
                    p[r][j] += __shfl_xor_sync(0xFFFFFFFFu, p[r][j], mask);
        float z[4];
        #pragma unroll
        for (int r = 0; r < 4; ++r) {
            z[r] = b7v;
            #pragma unroll
            for (int j = 0; j < 4; ++j)
                z[r] += fmaxf(p[r][j] + b6s[j], 0.f) * W7s[j];
        }
        if (t == 0) {
            float* o = out + row0;
            o[g]      = 1.0f / (1.0f + __expf(-z[0]));
            o[g + 8]  = 1.0f / (1.0f + __expf(-z[1]));
            o[g + 16] = 1.0f / (1.0f + __expf(-z[2]));
            o[g + 24] = 1.0f / (1.0f + __expf(-z[3]));
        }
    }
}

// ============================ launch ============================
extern "C" void kernel_launch(void* const* d_in, const int* in_sizes, int n_in,
                              void* d_out, int out_size) {
    cudaFuncSetAttribute(fused_mlp_kernel,
                         cudaFuncAttributeMaxDynamicSharedMemorySize, SMEM_BYTES);
    fused_mlp_kernel<<<NCTAS, NTHREADS, SMEM_BYTES>>>(
        (const float*)d_in[0],
        (const float*)d_in[1],  (const float*)d_in[2],
        (const float*)d_in[3],  (const float*)d_in[4],
        (const float*)d_in[5],  (const float*)d_in[6],
        (const float*)d_in[7],  (const float*)d_in[8],
        (const float*)d_in[9],  (const float*)d_in[10],
        (const float*)d_in[11], (const float*)d_in[12],
        (const float*)d_in[13], (const float*)d_in[14],
        (float*)d_out);
}